// round 13
// baseline (speedup 1.0000x reference)
#include <cuda_runtime.h>
#include <cuda_fp16.h>
#include <cstdint>
#include <math.h>

#define T 2048
#define H 1024
#define F 4096
#define E 8
#define NM 4
#define G 8
#define HG (H*G)      /* 8192  */
#define F2 (F/2)      /* 2048  */
#define FG2 (F2*G)    /* 16384 */

// ---------------- scratch (device globals; no allocation allowed) -------------
__device__ __half g_hsh[(size_t)T * H];              // fp16 hidden (GEMM A)
__device__ __half g_b1[(size_t)T * HG];              // fp16 rswaf(hidden)
__device__ __half g_midh[(size_t)NM * T * F];        // fp16 gelu(fc1)  (A of fc2)
__device__ float  g_k1[(size_t)4 * NM * T * F2];     // fp32 k1, 4 K-slices
__device__ __half g_b2[(size_t)NM * T * FG2];        // fp16 rswaf(k1)
__device__ float  g_outsk[16][(size_t)T * H];        // [slice*2+slot] outputs
__device__ int    g_tok[E][T];
__device__ float  g_wgt[E][T];
__device__ int    g_slot[E][T];
__device__ int    g_cnt[E];

// ---------------- helpers ------------------------------------------------------
__device__ __forceinline__ uint32_t pack_h2(float lo, float hi) {
    uint32_t r;
    asm("cvt.rn.f16x2.f32 %0, %2, %1;" : "=r"(r) : "f"(lo), "f"(hi));
    return r;
}
__device__ __forceinline__ void mma_f16(float* c, uint32_t a0, uint32_t a1,
                                        uint32_t a2, uint32_t a3,
                                        uint32_t b0, uint32_t b1) {
    asm volatile("mma.sync.aligned.m16n8k16.row.col.f32.f16.f16.f32 "
        "{%0,%1,%2,%3},{%4,%5,%6,%7},{%8,%9},{%0,%1,%2,%3};"
        : "+f"(c[0]), "+f"(c[1]), "+f"(c[2]), "+f"(c[3])
        : "r"(a0), "r"(a1), "r"(a2), "r"(a3), "r"(b0), "r"(b1));
}
__device__ __forceinline__ uint32_t smem_u32(const void* p) {
    uint32_t a;
    asm("{ .reg .u64 t; cvta.to.shared.u64 t, %1; cvt.u32.u64 %0, t; }" : "=r"(a) : "l"(p));
    return a;
}
#define LDSM_X4(r0, r1, r2, r3, addr) \
    asm volatile("ldmatrix.sync.aligned.m8n8.x4.shared.b16 {%0,%1,%2,%3}, [%4];" \
        : "=r"(r0), "=r"(r1), "=r"(r2), "=r"(r3) : "r"(addr))
#define CP_ASYNC16(dst, src) \
    asm volatile("cp.async.cg.shared.global [%0], [%1], 16;" :: "r"(dst), "l"(src))
#define CP_COMMIT()  asm volatile("cp.async.commit_group;" ::: "memory")
#define CP_WAIT0()   asm volatile("cp.async.wait_group 0;" ::: "memory")
#define CP_WAIT1()   asm volatile("cp.async.wait_group 1;" ::: "memory")

// ---------------- small kernels ------------------------------------------------
__global__ void zero_cnt_kernel() {
    if (threadIdx.x < E) g_cnt[threadIdx.x] = 0;
}

__global__ void router_kernel(const float* __restrict__ hs, const float* __restrict__ gw) {
    int t = blockIdx.x;
    int warp = threadIdx.x >> 5, lane = threadIdx.x & 31;
    const float* x = hs + (size_t)t * H;
    const float* g = gw + (size_t)warp * H;
    float s = 0.f;
    for (int k = lane; k < H; k += 32) s += x[k] * g[k];
    #pragma unroll
    for (int o = 16; o; o >>= 1) s += __shfl_xor_sync(0xFFFFFFFFu, s, o);
    __shared__ float logits[E];
    if (lane == 0) logits[warp] = s;
    __syncthreads();
    if (threadIdx.x == 0) {
        float l1 = -1e30f, l2 = -1e30f; int e1 = 0, e2 = 0;
        #pragma unroll
        for (int e = 0; e < E; e++) {
            float v = logits[e];
            if (v > l1) { l2 = l1; e2 = e1; l1 = v; e1 = e; }
            else if (v > l2) { l2 = v; e2 = e; }
        }
        float r  = expf(l2 - l1);
        float w1 = 1.0f / (1.0f + r);
        float w2 = r * w1;
        int p1 = atomicAdd(&g_cnt[e1], 1);
        g_tok[e1][p1] = t; g_wgt[e1][p1] = w1; g_slot[e1][p1] = 0;
        int p2 = atomicAdd(&g_cnt[e2], 1);
        g_tok[e2][p2] = t; g_wgt[e2][p2] = w2; g_slot[e2][p2] = 1;
    }
}

__device__ __forceinline__ void rswaf8(float x, __half* dst, size_t idx) {
    float r[8];
    #pragma unroll
    for (int i = 0; i < 8; i++) {
        float d = (x - (-1.2f + 0.2f * (float)i)) * 0.5f;
        float th = tanhf(d);
        r[i] = 1.0f - th * th;
    }
    uint4 u = make_uint4(pack_h2(r[0], r[1]), pack_h2(r[2], r[3]),
                         pack_h2(r[4], r[5]), pack_h2(r[6], r[7]));
    *(uint4*)(dst + idx * 8) = u;
}

// fused: blocks [0, 2048) convert hs -> fp16; blocks [2048, 10240) basis0
#define CVT_BLOCKS (T * H / 4 / 256)
__global__ void prep_kernel(const float* __restrict__ hs) {
    if ((int)blockIdx.x < CVT_BLOCKS) {
        int i = blockIdx.x * 256 + threadIdx.x;
        float4 v = ((const float4*)hs)[i];
        ((uint2*)g_hsh)[i] = make_uint2(pack_h2(v.x, v.y), pack_h2(v.z, v.w));
    } else {
        int idx = (blockIdx.x - CVT_BLOCKS) * 256 + threadIdx.x;
        rswaf8(hs[idx], g_b1, (size_t)idx);
    }
}

// basis over k1 (sums 4 split-K slices)
__global__ void basis1_kernel() {
    int idx = blockIdx.x * blockDim.x + threadIdx.x;
    int z = blockIdx.z;
    int row = idx / F2;
    if (row >= g_cnt[NM + z]) return;
    float x = g_k1[(size_t)(0 * NM + z) * T * F2 + idx] +
              g_k1[(size_t)(1 * NM + z) * T * F2 + idx] +
              g_k1[(size_t)(2 * NM + z) * T * F2 + idx] +
              g_k1[(size_t)(3 * NM + z) * T * F2 + idx];
    rswaf8(x, g_b2 + (size_t)z * T * FG2, (size_t)idx);
}

// ================= fp16 mma.sync GEMM v7: 256x128 tile, 64x64 warp tile ========
// BM=256, BN=128, BK=64, 256 threads (8 warps 4x2, warp tile 64x64), 1 CTA/SM.
// A ring: 3 stages (cp.async, issued 2 chunks ahead).  B ring: 2 stages.
#define BM 256
#define A_STAGE 32768                /* 256 rows x 128 B */
#define B_STAGE 16384                /* 128 rows x 128 B */
#define B_BASE (3 * A_STAGE)
#define SMEM_BYTES (3 * A_STAGE + 2 * B_STAGE)  /* 128 KB */

template<int MODE, int NSPLIT>
__global__ __launch_bounds__(256, 1)
void mma_gemm(const __half* __restrict__ Abase, size_t Aslab, int lda, int gather, int eoff,
              const float* __restrict__ Bbase, size_t Bslab,
              const float* __restrict__ biasbase, int biasslab,
              float* __restrict__ Cbase, __half* __restrict__ Chbase,
              size_t Cslab, int ldc, int K) {
    int z = blockIdx.z, expert = eoff + z;
    int cnt = g_cnt[expert];
    int by = blockIdx.y / NSPLIT;
    int slice = blockIdx.y % NSPLIT;
    int bx = blockIdx.x;
    if (by * BM >= cnt) return;

    int Kh = K / NSPLIT;
    uint32_t koff_a = (uint32_t)(slice * Kh) * 2u;
    uint32_t koff_b = (uint32_t)(slice * Kh) * 4u;

    extern __shared__ __align__(16) char smem[];
    uint32_t sb = smem_u32(smem);
    char* sB[2] = { smem + B_BASE, smem + B_BASE + B_STAGE };

    const __half* A = Abase + (size_t)z * Aslab;
    const float*  B = Bbase + (size_t)z * Bslab;

    int tid = threadIdx.x;
    int c  = tid & 7;        // 16B group within 128B row
    int r0 = tid >> 3;       // 0..31
    uint32_t a_off[8], stA[8];
    uint32_t b_off[4], stB[4];
    #pragma unroll
    for (int j = 0; j < 8; j++) {
        int row = r0 + 32 * j;          // A rows 0..255
        int arow;
        if (gather) {
            int gi = by * BM + row;
            if (gi >= cnt) gi = cnt - 1;
            arow = g_tok[expert][gi];
        } else {
            arow = by * BM + row;
        }
        a_off[j] = (uint32_t)arow * (uint32_t)lda * 2u + c * 16u + koff_a;
        stA[j]   = row * 128 + ((c ^ (row & 7)) << 4);
    }
    #pragma unroll
    for (int j = 0; j < 4; j++) {
        int row = r0 + 32 * j;          // B rows 0..127
        b_off[j] = (uint32_t)(bx * 128 + row) * (uint32_t)K * 4u + c * 32u + koff_b;
        stB[j]   = row * 128 + ((c ^ (row & 7)) << 4);
    }

    int wid = tid >> 5, lane = tid & 31;
    int wm = wid >> 1, wn = wid & 1;     // 4 x 2 warp grid; warp tile 64x64
    int gp = lane >> 2, tig = lane & 3;
    int r7 = lane & 7;

    uint32_t baseA = (uint32_t)(wm * 64 + (lane & 15)) * 128u;
    uint32_t baseB = (uint32_t)(wn * 64 + (lane & 7) + ((lane >> 4) << 3)) * 128u;
    uint32_t hiA = (lane >> 4) & 1;
    uint32_t hiB = (lane >> 3) & 1;
    uint32_t xa[4], xb[4];
    #pragma unroll
    for (int ks = 0; ks < 4; ks++) {
        xa[ks] = (uint32_t)(((2 * ks + hiA) ^ r7) << 4);
        xb[ks] = (uint32_t)(((2 * ks + hiB) ^ r7) << 4);
    }

    float acc[4][8][4];
    #pragma unroll
    for (int mt = 0; mt < 4; mt++)
        #pragma unroll
        for (int nt = 0; nt < 8; nt++)
            #pragma unroll
            for (int q = 0; q < 4; q++) acc[mt][nt][q] = 0.f;

    int nch = Kh >> 6;   // >= 8 in all configs

    // ---- prologue: A chunks 0 and 1 (separate groups), B chunk 0 ----
    #pragma unroll
    for (int j = 0; j < 8; j++)
        CP_ASYNC16(sb + stA[j], (const char*)A + a_off[j]);
    CP_COMMIT();
    #pragma unroll
    for (int j = 0; j < 8; j++)
        CP_ASYNC16(sb + A_STAGE + stA[j], (const char*)A + a_off[j] + 128u);
    CP_COMMIT();
    #pragma unroll
    for (int j = 0; j < 4; j++) {
        float4 v0 = *(const float4*)((const char*)B + b_off[j]);
        float4 v1 = *(const float4*)((const char*)B + b_off[j] + 16);
        uint4 u = make_uint4(pack_h2(v0.x, v0.y), pack_h2(v0.z, v0.w),
                             pack_h2(v1.x, v1.y), pack_h2(v1.z, v1.w));
        *(uint4*)(sB[0] + stB[j]) = u;
    }
    CP_WAIT1();
    __syncthreads();

    int sa_cur = 0;
    for (int i = 0; i < nch; i++) {
        bool pre = (i + 1 < nch);
        if (i + 2 < nch) {
            int sa_wr = sa_cur + 2; if (sa_wr >= 3) sa_wr -= 3;
            uint32_t ka2 = (uint32_t)(i + 2) * 128u;
            uint32_t dst_a = sb + (uint32_t)sa_wr * A_STAGE;
            #pragma unroll
            for (int j = 0; j < 8; j++)
                CP_ASYNC16(dst_a + stA[j], (const char*)A + a_off[j] + ka2);
            CP_COMMIT();
        }
        uint32_t aA = sb + (uint32_t)sa_cur * A_STAGE + baseA;
        uint32_t aB = sb + B_BASE + (uint32_t)(i & 1) * B_STAGE + baseB;

        uint32_t kb = (uint32_t)(i + 1) * 256u;
        float4 bb[2][2];
        if (pre) {
            #pragma unroll
            for (int j = 0; j < 2; j++) {
                bb[j][0] = *(const float4*)((const char*)B + b_off[j] + kb);
                bb[j][1] = *(const float4*)((const char*)B + b_off[j] + kb + 16);
            }
        }

        #pragma unroll
        for (int ks = 0; ks < 4; ks++) {
            if (ks == 2 && pre) {
                char* Bd = sB[(i + 1) & 1];
                #pragma unroll
                for (int j = 0; j < 2; j++) {
                    uint4 u = make_uint4(pack_h2(bb[j][0].x, bb[j][0].y), pack_h2(bb[j][0].z, bb[j][0].w),
                                         pack_h2(bb[j][1].x, bb[j][1].y), pack_h2(bb[j][1].z, bb[j][1].w));
                    *(uint4*)(Bd + stB[j]) = u;
                }
                #pragma unroll
                for (int j = 2; j < 4; j++) {
                    bb[j - 2][0] = *(const float4*)((const char*)B + b_off[j] + kb);
                    bb[j - 2][1] = *(const float4*)((const char*)B + b_off[j] + kb + 16);
                }
            }
            uint32_t bf[8][2];
            #pragma unroll
            for (int p = 0; p < 4; p++)
                LDSM_X4(bf[2*p][0], bf[2*p][1], bf[2*p+1][0], bf[2*p+1][1],
                        aB + p * 2048u + xb[ks]);
            #pragma unroll
            for (int mt = 0; mt < 4; mt++) {
                uint32_t a0, a1, a2, a3;
                LDSM_X4(a0, a1, a2, a3, aA + mt * 2048u + xa[ks]);
                #pragma unroll
                for (int nt = 0; nt < 8; nt++)
                    mma_f16(acc[mt][nt], a0, a1, a2, a3, bf[nt][0], bf[nt][1]);
            }
        }

        if (pre) {
            char* Bd = sB[(i + 1) & 1];
            #pragma unroll
            for (int j = 2; j < 4; j++) {
                uint4 u = make_uint4(pack_h2(bb[j-2][0].x, bb[j-2][0].y), pack_h2(bb[j-2][0].z, bb[j-2][0].w),
                                     pack_h2(bb[j-2][1].x, bb[j-2][1].y), pack_h2(bb[j-2][1].z, bb[j-2][1].w));
                *(uint4*)(Bd + stB[j]) = u;
            }
            if (i + 2 < nch) { CP_WAIT1(); } else { CP_WAIT0(); }
        }
        __syncthreads();
        sa_cur = (sa_cur + 1 == 3) ? 0 : sa_cur + 1;
    }

    // ---- epilogue ----
    const float* bias = nullptr;
    if (MODE == 0) bias = biasbase + (size_t)z * biasslab;
    if (MODE == 2 && biasbase && slice == 0) bias = biasbase + (size_t)z * biasslab;

    #pragma unroll
    for (int mt = 0; mt < 4; mt++) {
        #pragma unroll
        for (int half = 0; half < 2; half++) {
            int row = by * BM + wm * 64 + mt * 16 + gp + half * 8;
            if (row >= cnt) continue;
            float* dst = nullptr; __half* dsth = nullptr;
            float wv = 1.f;
            if (MODE == 0) {
                dsth = Chbase + (size_t)z * Cslab + (size_t)row * ldc;
            } else if (MODE == 1) {
                dst = Cbase + (size_t)(slice * NM + z) * Cslab + (size_t)row * ldc;
            } else {
                int   t  = g_tok[expert][row];
                int   sl = g_slot[expert][row];
                wv = g_wgt[expert][row];
                dst = &g_outsk[slice * 2 + sl][(size_t)t * H];
            }
            #pragma unroll
            for (int nt = 0; nt < 8; nt++) {
                int col = bx * 128 + wn * 64 + nt * 8 + 2 * tig;
                float v0 = acc[mt][nt][half * 2];
                float v1 = acc[mt][nt][half * 2 + 1];
                if (MODE == 0) {
                    v0 += bias[col];     v1 += bias[col + 1];
                    v0 = 0.5f * v0 * (1.0f + erff(v0 * 0.70710678118654752f));
                    v1 = 0.5f * v1 * (1.0f + erff(v1 * 0.70710678118654752f));
                    *(uint32_t*)(dsth + col) = pack_h2(v0, v1);
                } else if (MODE == 2) {
                    if (bias) { v0 += bias[col]; v1 += bias[col + 1]; }
                    *(float2*)(dst + col) = make_float2(v0 * wv, v1 * wv);
                } else {
                    *(float2*)(dst + col) = make_float2(v0, v1);
                }
            }
        }
    }
}

__global__ void combine_kernel(float* __restrict__ out) {
    int i = blockIdx.x * blockDim.x + threadIdx.x;
    float sx = 0.f, sy = 0.f, sz = 0.f, sw = 0.f;
    #pragma unroll
    for (int j = 0; j < 16; j++) {
        float4 v = ((const float4*)g_outsk[j])[i];
        sx += v.x; sy += v.y; sz += v.z; sw += v.w;
    }
    ((float4*)out)[i] = make_float4(sx, sy, sz, sw);
}

// ---------------- launch --------------------------------------------------------
extern "C" void kernel_launch(void* const* d_in, const int* in_sizes, int n_in,
                              void* d_out, int out_size) {
    const float* hs     = (const float*)d_in[0];
    const float* gate_w = (const float*)d_in[1];
    const float* fc1_w  = (const float*)d_in[2];
    const float* fc1_b  = (const float*)d_in[3];
    const float* fc2_w  = (const float*)d_in[4];
    const float* fc2_b  = (const float*)d_in[5];
    const float* sp1_w  = (const float*)d_in[6];
    const float* sp2_w  = (const float*)d_in[7];
    float* out = (float*)d_out;

    __half *p_hsh = nullptr, *p_midh = nullptr, *p_b1 = nullptr, *p_b2 = nullptr;
    float  *p_k1 = nullptr;
    cudaGetSymbolAddress((void**)&p_hsh,  g_hsh);
    cudaGetSymbolAddress((void**)&p_b1,   g_b1);
    cudaGetSymbolAddress((void**)&p_midh, g_midh);
    cudaGetSymbolAddress((void**)&p_k1,   g_k1);
    cudaGetSymbolAddress((void**)&p_b2,   g_b2);

    cudaFuncSetAttribute(mma_gemm<0,1>, cudaFuncAttributeMaxDynamicSharedMemorySize, SMEM_BYTES);
    cudaFuncSetAttribute(mma_gemm<1,4>, cudaFuncAttributeMaxDynamicSharedMemorySize, SMEM_BYTES);
    cudaFuncSetAttribute(mma_gemm<2,8>, cudaFuncAttributeMaxDynamicSharedMemorySize, SMEM_BYTES);

    zero_cnt_kernel<<<1, 32>>>();
    router_kernel<<<T, 256>>>(hs, gate_w);
    prep_kernel<<<CVT_BLOCKS + (T * H) / 256, 256>>>(hs);

    // MLP experts (routing experts 0..3)
    mma_gemm<0,1><<<dim3(F / 128, T / BM, NM), 256, SMEM_BYTES>>>(
        p_hsh, 0, H, /*gather=*/1, /*eoff=*/0,
        fc1_w, (size_t)F * H,
        fc1_b, F,
        nullptr, p_midh, (size_t)T * F, F,
        H);
    mma_gemm<2,8><<<dim3(H / 128, (T / BM) * 8, NM), 256, SMEM_BYTES>>>(
        p_midh, (size_t)T * F, F, /*gather=*/0, /*eoff=*/0,
        fc2_w, (size_t)H * F,
        fc2_b, H,
        nullptr, nullptr, 0, 0,
        F);

    // KAN experts (routing experts 4..7)
    mma_gemm<1,4><<<dim3(F2 / 128, (T / BM) * 4, NM), 256, SMEM_BYTES>>>(
        p_b1, 0, HG, /*gather=*/1, /*eoff=*/NM,
        sp1_w, (size_t)F2 * HG,
        nullptr, 0,
        p_k1, nullptr, (size_t)T * F2, F2,
        HG);
    basis1_kernel<<<dim3((T * F2) / 256, 1, NM), 256>>>();
    mma_gemm<2,8><<<dim3(H / 128, (T / BM) * 8, NM), 256, SMEM_BYTES>>>(
        p_b2, (size_t)T * FG2, FG2, /*gather=*/0, /*eoff=*/NM,
        sp2_w, (size_t)H * FG2,
        nullptr, 0,
        nullptr, nullptr, 0, 0,
        FG2);

    combine_kernel<<<(T * H / 4) / 256, 256>>>(out);
}

// round 14
// speedup vs baseline: 1.3439x; 1.3439x over previous
#include <cuda_runtime.h>
#include <cuda_fp16.h>
#include <cstdint>
#include <math.h>

#define T 2048
#define H 1024
#define F 4096
#define E 8
#define NM 4
#define G 8
#define HG (H*G)      /* 8192  */
#define F2 (F/2)      /* 2048  */
#define FG2 (F2*G)    /* 16384 */

// ---------------- scratch (device globals; no allocation allowed) -------------
__device__ __half g_hsh[(size_t)T * H];              // fp16 hidden (GEMM A)
__device__ __half g_b1[(size_t)T * HG];              // fp16 rswaf(hidden)
__device__ __half g_midh[(size_t)NM * T * F];        // fp16 gelu(fc1)  (A of fc2)
__device__ __half g_b2[(size_t)NM * T * FG2];        // fp16 rswaf(k1) (sp1 epilogue)
__device__ float  g_outsk[8][(size_t)T * H];         // [slice*2+slot] outputs
__device__ int    g_tok[E][T];
__device__ float  g_wgt[E][T];
__device__ int    g_slot[E][T];
__device__ int    g_cnt[E];

// ---------------- helpers ------------------------------------------------------
__device__ __forceinline__ uint32_t pack_h2(float lo, float hi) {
    uint32_t r;
    asm("cvt.rn.f16x2.f32 %0, %2, %1;" : "=r"(r) : "f"(lo), "f"(hi));
    return r;
}
__device__ __forceinline__ float tanh_fast(float x) {
    float y;
    asm("tanh.approx.f32 %0, %1;" : "=f"(y) : "f"(x));
    return y;
}
__device__ __forceinline__ void mma_f16(float* c, uint32_t a0, uint32_t a1,
                                        uint32_t a2, uint32_t a3,
                                        uint32_t b0, uint32_t b1) {
    asm volatile("mma.sync.aligned.m16n8k16.row.col.f32.f16.f16.f32 "
        "{%0,%1,%2,%3},{%4,%5,%6,%7},{%8,%9},{%0,%1,%2,%3};"
        : "+f"(c[0]), "+f"(c[1]), "+f"(c[2]), "+f"(c[3])
        : "r"(a0), "r"(a1), "r"(a2), "r"(a3), "r"(b0), "r"(b1));
}
__device__ __forceinline__ uint32_t smem_u32(const void* p) {
    uint32_t a;
    asm("{ .reg .u64 t; cvta.to.shared.u64 t, %1; cvt.u32.u64 %0, t; }" : "=r"(a) : "l"(p));
    return a;
}
#define LDSM_X4(r0, r1, r2, r3, addr) \
    asm volatile("ldmatrix.sync.aligned.m8n8.x4.shared.b16 {%0,%1,%2,%3}, [%4];" \
        : "=r"(r0), "=r"(r1), "=r"(r2), "=r"(r3) : "r"(addr))
#define CP_ASYNC16(dst, src) \
    asm volatile("cp.async.cg.shared.global [%0], [%1], 16;" :: "r"(dst), "l"(src))
#define CP_COMMIT()  asm volatile("cp.async.commit_group;" ::: "memory")
#define CP_WAIT0()   asm volatile("cp.async.wait_group 0;" ::: "memory")

// rswaf basis of one value -> 8 fp16 packed in uint4
__device__ __forceinline__ uint4 rswaf_pack(float x) {
    float r[8];
    #pragma unroll
    for (int i = 0; i < 8; i++) {
        float th = tanh_fast((x - (-1.2f + 0.2f * (float)i)) * 0.5f);
        r[i] = 1.0f - th * th;
    }
    return make_uint4(pack_h2(r[0], r[1]), pack_h2(r[2], r[3]),
                      pack_h2(r[4], r[5]), pack_h2(r[6], r[7]));
}

// ---------------- small kernels ------------------------------------------------
__global__ void zero_cnt_kernel() {
    if (threadIdx.x < E) g_cnt[threadIdx.x] = 0;
}

__global__ void router_kernel(const float* __restrict__ hs, const float* __restrict__ gw) {
    int t = blockIdx.x;
    int warp = threadIdx.x >> 5, lane = threadIdx.x & 31;
    const float* x = hs + (size_t)t * H;
    const float* g = gw + (size_t)warp * H;
    float s = 0.f;
    for (int k = lane; k < H; k += 32) s += x[k] * g[k];
    #pragma unroll
    for (int o = 16; o; o >>= 1) s += __shfl_xor_sync(0xFFFFFFFFu, s, o);
    __shared__ float logits[E];
    if (lane == 0) logits[warp] = s;
    __syncthreads();
    if (threadIdx.x == 0) {
        float l1 = -1e30f, l2 = -1e30f; int e1 = 0, e2 = 0;
        #pragma unroll
        for (int e = 0; e < E; e++) {
            float v = logits[e];
            if (v > l1) { l2 = l1; e2 = e1; l1 = v; e1 = e; }
            else if (v > l2) { l2 = v; e2 = e; }
        }
        float r  = expf(l2 - l1);
        float w1 = 1.0f / (1.0f + r);
        float w2 = r * w1;
        int p1 = atomicAdd(&g_cnt[e1], 1);
        g_tok[e1][p1] = t; g_wgt[e1][p1] = w1; g_slot[e1][p1] = 0;
        int p2 = atomicAdd(&g_cnt[e2], 1);
        g_tok[e2][p2] = t; g_wgt[e2][p2] = w2; g_slot[e2][p2] = 1;
    }
}

// fused: blocks [0, 2048) convert hs -> fp16; blocks [2048, 10240) basis0
#define CVT_BLOCKS (T * H / 4 / 256)
__global__ void prep_kernel(const float* __restrict__ hs) {
    if ((int)blockIdx.x < CVT_BLOCKS) {
        int i = blockIdx.x * 256 + threadIdx.x;
        float4 v = ((const float4*)hs)[i];
        ((uint2*)g_hsh)[i] = make_uint2(pack_h2(v.x, v.y), pack_h2(v.z, v.w));
    } else {
        int idx = (blockIdx.x - CVT_BLOCKS) * 256 + threadIdx.x;
        ((uint4*)g_b1)[idx] = rswaf_pack(hs[idx]);
    }
}

// ================= fp16 mma.sync GEMM (round-9 core) ===========================
// 128x128 tile, BK=64, 128 threads (4 warps 2x2, warp tile 64x64), 2 CTAs/SM.
// MODE 0: Ch = half(gelu(acc + bias)) -> g_midh
// MODE 2: out = wgt * (acc [+bias on slice0]) -> g_outsk[slice*2+slot]
// MODE 3: b2 rows = rswaf(acc) -> g_b2 (sp1 with fused basis; NSPLIT must be 1)
#define STAGE_BYTES 16384            /* 128 rows x 128 B (64 halves) */
#define SMEM_BYTES (4 * STAGE_BYTES) /* A0 A1 B0 B1 = 64KB */

template<int MODE, int NSPLIT>
__global__ __launch_bounds__(128, 2)
void mma_gemm(const __half* __restrict__ Abase, size_t Aslab, int lda, int gather, int eoff,
              const float* __restrict__ Bbase, size_t Bslab,
              const float* __restrict__ biasbase, int biasslab,
              __half* __restrict__ Chbase, size_t Cslab, int ldc, int K) {
    int z = blockIdx.z, expert = eoff + z;
    int cnt = g_cnt[expert];
    int by = blockIdx.y / NSPLIT;
    int slice = blockIdx.y % NSPLIT;
    int bx = blockIdx.x;
    if (by * 128 >= cnt) return;

    int Kh = K / NSPLIT;
    uint32_t koff_a = (uint32_t)(slice * Kh) * 2u;
    uint32_t koff_b = (uint32_t)(slice * Kh) * 4u;

    extern __shared__ __align__(16) char smem[];
    uint32_t sb = smem_u32(smem);
    char* sB[2] = { smem + 2 * STAGE_BYTES, smem + 3 * STAGE_BYTES };

    const __half* A = Abase + (size_t)z * Aslab;
    const float*  B = Bbase + (size_t)z * Bslab;

    int tid = threadIdx.x;
    int c  = tid & 7;
    int r0 = tid >> 3;
    uint32_t a_off[8], b_off[8], st_byte[8];
    #pragma unroll
    for (int j = 0; j < 8; j++) {
        int row = r0 + 16 * j;
        int arow;
        if (gather) {
            int gi = by * 128 + row;
            if (gi >= cnt) gi = cnt - 1;
            arow = g_tok[expert][gi];
        } else {
            arow = by * 128 + row;
        }
        a_off[j]  = (uint32_t)arow * (uint32_t)lda * 2u + c * 16u + koff_a;
        b_off[j]  = (uint32_t)(bx * 128 + row) * (uint32_t)K * 4u + c * 32u + koff_b;
        st_byte[j] = row * 128 + ((c ^ (row & 7)) << 4);
    }

    int wid = tid >> 5, lane = tid & 31;
    int wm = wid >> 1, wn = wid & 1;
    int gp = lane >> 2, tig = lane & 3;
    int r7 = lane & 7;

    uint32_t baseA = (uint32_t)(wm * 64 + (lane & 15)) * 128u;
    uint32_t baseB = (uint32_t)(wn * 64 + (lane & 7) + ((lane >> 4) << 3)) * 128u;
    uint32_t hiA = (lane >> 4) & 1;
    uint32_t hiB = (lane >> 3) & 1;
    uint32_t xa[4], xb[4];
    #pragma unroll
    for (int ks = 0; ks < 4; ks++) {
        xa[ks] = (uint32_t)(((2 * ks + hiA) ^ r7) << 4);
        xb[ks] = (uint32_t)(((2 * ks + hiB) ^ r7) << 4);
    }

    float acc[4][8][4];
    #pragma unroll
    for (int mt = 0; mt < 4; mt++)
        #pragma unroll
        for (int nt = 0; nt < 8; nt++)
            #pragma unroll
            for (int q = 0; q < 4; q++) acc[mt][nt][q] = 0.f;

    int nch = Kh >> 6;

    // ---- prologue: stage chunk 0 ----
    #pragma unroll
    for (int j = 0; j < 8; j++)
        CP_ASYNC16(sb + st_byte[j], (const char*)A + a_off[j]);
    CP_COMMIT();
    #pragma unroll
    for (int j = 0; j < 8; j++) {
        float4 v0 = *(const float4*)((const char*)B + b_off[j]);
        float4 v1 = *(const float4*)((const char*)B + b_off[j] + 16);
        uint4 u = make_uint4(pack_h2(v0.x, v0.y), pack_h2(v0.z, v0.w),
                             pack_h2(v1.x, v1.y), pack_h2(v1.z, v1.w));
        *(uint4*)(sB[0] + st_byte[j]) = u;
    }
    CP_WAIT0();
    __syncthreads();

    for (int i = 0; i < nch; i++) {
        int s = i & 1;
        bool pre = (i + 1 < nch);
        uint32_t ka = (uint32_t)(i + 1) * 128u;
        uint32_t kb = (uint32_t)(i + 1) * 256u;
        if (pre) {
            uint32_t dst_a = sb + (s ^ 1) * STAGE_BYTES;
            #pragma unroll
            for (int j = 0; j < 8; j++)
                CP_ASYNC16(dst_a + st_byte[j], (const char*)A + a_off[j] + ka);
            CP_COMMIT();
        }
        uint32_t aA = sb + s * STAGE_BYTES + baseA;
        uint32_t aB = sb + (2 + s) * STAGE_BYTES + baseB;

        float4 bb[4][2];
        if (pre) {
            #pragma unroll
            for (int j = 0; j < 4; j++) {
                bb[j][0] = *(const float4*)((const char*)B + b_off[j] + kb);
                bb[j][1] = *(const float4*)((const char*)B + b_off[j] + kb + 16);
            }
        }

        #pragma unroll
        for (int ks = 0; ks < 4; ks++) {
            if (ks == 2 && pre) {
                char* Bd = sB[s ^ 1];
                #pragma unroll
                for (int j = 0; j < 4; j++) {
                    uint4 u = make_uint4(pack_h2(bb[j][0].x, bb[j][0].y), pack_h2(bb[j][0].z, bb[j][0].w),
                                         pack_h2(bb[j][1].x, bb[j][1].y), pack_h2(bb[j][1].z, bb[j][1].w));
                    *(uint4*)(Bd + st_byte[j]) = u;
                }
                #pragma unroll
                for (int j = 4; j < 8; j++) {
                    bb[j - 4][0] = *(const float4*)((const char*)B + b_off[j] + kb);
                    bb[j - 4][1] = *(const float4*)((const char*)B + b_off[j] + kb + 16);
                }
            }
            uint32_t bf[8][2];
            #pragma unroll
            for (int p = 0; p < 4; p++)
                LDSM_X4(bf[2*p][0], bf[2*p][1], bf[2*p+1][0], bf[2*p+1][1],
                        aB + p * 2048u + xb[ks]);
            #pragma unroll
            for (int mt = 0; mt < 4; mt++) {
                uint32_t a0, a1, a2, a3;
                LDSM_X4(a0, a1, a2, a3, aA + mt * 2048u + xa[ks]);
                #pragma unroll
                for (int nt = 0; nt < 8; nt++)
                    mma_f16(acc[mt][nt], a0, a1, a2, a3, bf[nt][0], bf[nt][1]);
            }
        }

        if (pre) {
            char* Bd = sB[s ^ 1];
            #pragma unroll
            for (int j = 4; j < 8; j++) {
                uint4 u = make_uint4(pack_h2(bb[j-4][0].x, bb[j-4][0].y), pack_h2(bb[j-4][0].z, bb[j-4][0].w),
                                     pack_h2(bb[j-4][1].x, bb[j-4][1].y), pack_h2(bb[j-4][1].z, bb[j-4][1].w));
                *(uint4*)(Bd + st_byte[j]) = u;
            }
            CP_WAIT0();
        }
        __syncthreads();
    }

    // ---- epilogue ----
    const float* bias = nullptr;
    if (MODE == 0) bias = biasbase + (size_t)z * biasslab;
    if (MODE == 2 && biasbase && slice == 0) bias = biasbase + (size_t)z * biasslab;

    #pragma unroll
    for (int mt = 0; mt < 4; mt++) {
        #pragma unroll
        for (int half = 0; half < 2; half++) {
            int row = by * 128 + wm * 64 + mt * 16 + gp + half * 8;
            if (row >= cnt) continue;
            __half* dsth = nullptr;
            float* dst = nullptr;
            float wv = 1.f;
            if (MODE == 0) {
                dsth = Chbase + (size_t)z * Cslab + (size_t)row * ldc;
            } else if (MODE == 3) {
                dsth = g_b2 + (size_t)z * T * FG2 + (size_t)row * FG2;
            } else {
                int   t  = g_tok[expert][row];
                int   sl = g_slot[expert][row];
                wv = g_wgt[expert][row];
                dst = &g_outsk[slice * 2 + sl][(size_t)t * H];
            }
            #pragma unroll
            for (int nt = 0; nt < 8; nt++) {
                int col = bx * 128 + wn * 64 + nt * 8 + 2 * tig;
                float v0 = acc[mt][nt][half * 2];
                float v1 = acc[mt][nt][half * 2 + 1];
                if (MODE == 0) {
                    v0 += bias[col];     v1 += bias[col + 1];
                    v0 = 0.5f * v0 * (1.0f + erff(v0 * 0.70710678118654752f));
                    v1 = 0.5f * v1 * (1.0f + erff(v1 * 0.70710678118654752f));
                    *(uint32_t*)(dsth + col) = pack_h2(v0, v1);
                } else if (MODE == 3) {
                    // fused rswaf basis: each k1 value expands to 8 fp16
                    *(uint4*)(dsth + (size_t)col * 8)     = rswaf_pack(v0);
                    *(uint4*)(dsth + (size_t)col * 8 + 8) = rswaf_pack(v1);
                } else {
                    if (bias) { v0 += bias[col]; v1 += bias[col + 1]; }
                    *(float2*)(dst + col) = make_float2(v0 * wv, v1 * wv);
                }
            }
        }
    }
}

__global__ void combine_kernel(float* __restrict__ out) {
    int i = blockIdx.x * blockDim.x + threadIdx.x;
    float sx = 0.f, sy = 0.f, sz = 0.f, sw = 0.f;
    #pragma unroll
    for (int j = 0; j < 8; j++) {
        float4 v = ((const float4*)g_outsk[j])[i];
        sx += v.x; sy += v.y; sz += v.z; sw += v.w;
    }
    ((float4*)out)[i] = make_float4(sx, sy, sz, sw);
}

// ---------------- launch --------------------------------------------------------
extern "C" void kernel_launch(void* const* d_in, const int* in_sizes, int n_in,
                              void* d_out, int out_size) {
    const float* hs     = (const float*)d_in[0];
    const float* gate_w = (const float*)d_in[1];
    const float* fc1_w  = (const float*)d_in[2];
    const float* fc1_b  = (const float*)d_in[3];
    const float* fc2_w  = (const float*)d_in[4];
    const float* fc2_b  = (const float*)d_in[5];
    const float* sp1_w  = (const float*)d_in[6];
    const float* sp2_w  = (const float*)d_in[7];
    float* out = (float*)d_out;

    __half *p_hsh = nullptr, *p_midh = nullptr, *p_b1 = nullptr, *p_b2 = nullptr;
    cudaGetSymbolAddress((void**)&p_hsh,  g_hsh);
    cudaGetSymbolAddress((void**)&p_b1,   g_b1);
    cudaGetSymbolAddress((void**)&p_midh, g_midh);
    cudaGetSymbolAddress((void**)&p_b2,   g_b2);

    cudaFuncSetAttribute(mma_gemm<0,1>, cudaFuncAttributeMaxDynamicSharedMemorySize, SMEM_BYTES);
    cudaFuncSetAttribute(mma_gemm<3,1>, cudaFuncAttributeMaxDynamicSharedMemorySize, SMEM_BYTES);
    cudaFuncSetAttribute(mma_gemm<2,4>, cudaFuncAttributeMaxDynamicSharedMemorySize, SMEM_BYTES);

    zero_cnt_kernel<<<1, 32>>>();
    router_kernel<<<T, 256>>>(hs, gate_w);
    prep_kernel<<<CVT_BLOCKS + (T * H) / 256, 256>>>(hs);

    // MLP experts (routing experts 0..3)
    mma_gemm<0,1><<<dim3(F / 128, 16, NM), 128, SMEM_BYTES>>>(
        p_hsh, 0, H, /*gather=*/1, /*eoff=*/0,
        fc1_w, (size_t)F * H,
        fc1_b, F,
        p_midh, (size_t)T * F, F,
        H);
    mma_gemm<2,4><<<dim3(H / 128, 16 * 4, NM), 128, SMEM_BYTES>>>(
        p_midh, (size_t)T * F, F, /*gather=*/0, /*eoff=*/0,
        fc2_w, (size_t)H * F,
        fc2_b, H,
        nullptr, 0, 0,
        F);

    // KAN experts (routing experts 4..7): sp1 with fused rswaf basis epilogue
    mma_gemm<3,1><<<dim3(F2 / 128, 16, NM), 128, SMEM_BYTES>>>(
        p_b1, 0, HG, /*gather=*/1, /*eoff=*/NM,
        sp1_w, (size_t)F2 * HG,
        nullptr, 0,
        nullptr, 0, 0,
        HG);
    mma_gemm<2,4><<<dim3(H / 128, 16 * 4, NM), 128, SMEM_BYTES>>>(
        p_b2, (size_t)T * FG2, FG2, /*gather=*/0, /*eoff=*/NM,
        sp2_w, (size_t)H * FG2,
        nullptr, 0,
        nullptr, 0, 0,
        FG2);

    combine_kernel<<<(T * H / 4) / 256, 256>>>(out);
}